// round 16
// baseline (speedup 1.0000x reference)
#include <cuda_runtime.h>
#include <cuda_fp16.h>
#include <cstdint>

#define NB   4
#define SEQ  4096
#define EMB  512
#define NTOK (NB * SEQ)   // 16384

// ---------------------------------------------------------------------------
// Device scratch
// ---------------------------------------------------------------------------
__device__ __half g_vh[(size_t)NTOK * EMB];
__device__ __half g_kh[(size_t)NTOK * EMB];
__device__ __half g_qh[(size_t)NTOK * EMB];
__device__ __half g_Wvh[EMB * EMB], g_Wvl[EMB * EMB];
__device__ __half g_Wkh[EMB * EMB], g_Wkl[EMB * EMB];
__device__ __half g_Wqh[EMB * EMB], g_Wql[EMB * EMB];
__device__ __half g_Woh[EMB * EMB], g_Wol[EMB * EMB];
__device__ __half g_Qph[(size_t)NTOK * EMB];                        // hi only
__device__ __half g_Kph[(size_t)NTOK * EMB];                        // hi only
__device__ __half g_VTh[(size_t)NTOK * EMB];                        // hi only, [b][d][l]
__device__ __half g_Eh [(size_t)NB * SEQ * SEQ];                    // scaled fp16 energy
__device__ __half g_Ph [(size_t)NB * SEQ * SEQ];                    // hi only
__device__ __half g_AOh[(size_t)NTOK * EMB];                        // hi only

// ---------------------------------------------------------------------------
// helpers
// ---------------------------------------------------------------------------
__device__ __forceinline__ uint32_t smem_u32_of(const void* p) {
    uint32_t a;
    asm("{ .reg .u64 t; cvta.to.shared.u64 t, %1; cvt.u32.u64 %0, t; }" : "=r"(a) : "l"(p));
    return a;
}

__device__ __forceinline__ void ldsm4(uint32_t* r, uint32_t addr) {
    asm volatile("ldmatrix.sync.aligned.m8n8.x4.shared.b16 {%0,%1,%2,%3}, [%4];"
                 : "=r"(r[0]), "=r"(r[1]), "=r"(r[2]), "=r"(r[3]) : "r"(addr));
}

__device__ __forceinline__ void mma16816(float* c, const uint32_t* a, const uint32_t* b) {
    asm volatile(
        "mma.sync.aligned.m16n8k16.row.col.f32.f16.f16.f32 "
        "{%0,%1,%2,%3}, {%4,%5,%6,%7}, {%8,%9}, {%0,%1,%2,%3};"
        : "+f"(c[0]), "+f"(c[1]), "+f"(c[2]), "+f"(c[3])
        : "r"(a[0]), "r"(a[1]), "r"(a[2]), "r"(a[3]), "r"(b[0]), "r"(b[1]));
}

#define CP_ASYNC16(dst, src) \
    asm volatile("cp.async.cg.shared.global [%0], [%1], 16;" :: "r"(dst), "l"(src))
#define CP_COMMIT() asm volatile("cp.async.commit_group;")
#define CP_WAIT(n)  asm volatile("cp.async.wait_group %0;" :: "n"(n))

__device__ __forceinline__ uint32_t packh2(__half a, __half b) {
    __half2 h = __halves2half2(a, b);
    return *(uint32_t*)&h;
}

#define STAGES 3
#define STAGES1 2
#define SOFT_SCALE 0.044194173824159216f   // 1/sqrt(512)

// smem offset helpers
// CHUNK=32: packed 2-rows-per-128B (tile 128 x 32 halves = 8 KB), u in 0..3
// CHUNK=64: plain 128B rows        (tile 128 x 64 halves = 16 KB), u in 0..7
template <int CHUNK>
__device__ __forceinline__ uint32_t foff(int row, int u) {
    uint32_t off;
    if (CHUNK == 64) off = (uint32_t)(row * 128 + u * 16);
    else             off = (uint32_t)(((row >> 1) << 7) | ((row & 1) << 6) | (u << 4));
    return off ^ ((off >> 3) & 0x70);
}

// ---------------------------------------------------------------------------
// 1-term GEMM kernel: 128 threads, warp tile 64x64 (2x2), CTA tile 128x128,
// chunk 64, 2 smem stages, occupancy 3.  (R12/R14 form, unchanged)
// EPI: 2 = scaled fp16 (energy); 4 = fp16 hi only
// ---------------------------------------------------------------------------
template <int EPI>
__global__ void __launch_bounds__(128, 3)
mma_gemm1(const __half* __restrict__ Ah, const __half* __restrict__ Bh,
          __half* __restrict__ Coh,
          int K, int ldC, long long sA, long long sB, long long sC)
{
    extern __shared__ __align__(1024) char smem[];
    const uint32_t smem_base = smem_u32_of(smem);
    constexpr uint32_t TB = 16384u;
    constexpr uint32_t STAGE_B = 2 * TB;

    const int tid = threadIdx.x;
    const int lane = tid & 31;
    const int w = tid >> 5;
    const int wm = w >> 1, wn = w & 1;
    const int z = blockIdx.z;
    const int bm = blockIdx.y * 128;
    const int bn = blockIdx.x * 128;

    const __half* gAh = Ah + (long long)z * sA + (long long)bm * K;
    const __half* gBh = Bh + (long long)z * sB + (long long)bn * K;

    const int ld_row = tid >> 3;
    const int ld_u   = tid & 7;

    const int a_row0 = wm * 64 + (lane & 15);
    const int a_uadd = lane >> 4;
    const int b_row0 = wn * 64 + (lane & 7) + ((lane >> 4) << 3);
    const int b_uadd = (lane >> 3) & 1;

    auto load_chunk = [&](int c) {
        const uint32_t sb = smem_base + (uint32_t)(c % STAGES1) * STAGE_B;
        const long long koff = (long long)c * 64;
        const __half* gp[2] = { gAh + koff, gBh + koff };
#pragma unroll
        for (int t = 0; t < 2; ++t) {
#pragma unroll
            for (int i = 0; i < 8; ++i) {
                const int row = ld_row + i * 16;
                const void* g = gp[t] + (long long)row * K + ld_u * 8;
                CP_ASYNC16(sb + t * TB + foff<64>(row, ld_u), g);
            }
        }
        CP_COMMIT();
    };

    float acc[4][8][4] = {};

    const int nCh = K >> 6;
#pragma unroll 1
    for (int c = 0; c < STAGES1; ++c) load_chunk(c);

#pragma unroll 1
    for (int c = 0; c < nCh; ++c) {
        CP_WAIT(STAGES1 - 1);
        __syncthreads();
        const uint32_t sb = smem_base + (uint32_t)(c % STAGES1) * STAGE_B;

#pragma unroll
        for (int ks = 0; ks < 4; ++ks) {
            uint32_t bF[8][2];
#pragma unroll
            for (int nh = 0; nh < 4; ++nh) {
                uint32_t r4[4];
                ldsm4(r4, sb + TB + foff<64>(b_row0 + nh * 16, ks * 2 + b_uadd));
                bF[2 * nh][0] = r4[0]; bF[2 * nh][1] = r4[1];
                bF[2 * nh + 1][0] = r4[2]; bF[2 * nh + 1][1] = r4[3];
            }
#pragma unroll
            for (int mf = 0; mf < 4; ++mf) {
                uint32_t aF[4];
                ldsm4(aF, sb + foff<64>(a_row0 + mf * 16, ks * 2 + a_uadd));
#pragma unroll
                for (int nf = 0; nf < 8; ++nf)
                    mma16816(acc[mf][nf], aF, bF[nf]);
            }
        }

        __syncthreads();
        if (c + STAGES1 < nCh) load_chunk(c + STAGES1);
        else CP_COMMIT();
    }

    // epilogue: warp tile 64x64
    const int g = lane >> 2, tig = lane & 3;
#pragma unroll
    for (int mf = 0; mf < 4; ++mf) {
#pragma unroll
        for (int h2 = 0; h2 < 2; ++h2) {
            const int row = bm + wm * 64 + mf * 16 + g + h2 * 8;
#pragma unroll
            for (int nf = 0; nf < 8; ++nf) {
                const int col = bn + wn * 64 + nf * 8 + 2 * tig;
                const float x0 = acc[mf][nf][h2 * 2 + 0];
                const float x1 = acc[mf][nf][h2 * 2 + 1];
                const long long base = (long long)z * sC + (long long)row * ldC + col;
                if (EPI == 2) {
                    *(uint32_t*)(Coh + base) =
                        packh2(__float2half(x0 * SOFT_SCALE), __float2half(x1 * SOFT_SCALE));
                } else {
                    *(uint32_t*)(Coh + base) = packh2(__float2half(x0), __float2half(x1));
                }
            }
        }
    }
}

// ---------------------------------------------------------------------------
// NEW 2-term GEMM core: 128 threads, warp tile 64x64 (2x2), chunk 32,
// 3 stages (24 KB each), occupancy 3. Term-by-term B processing
// (bH MMAs then bL MMAs) keeps per-accumulator order identical to before.
// ---------------------------------------------------------------------------
__device__ __forceinline__ void gemm2_core(
    const __half* __restrict__ gAh,
    const __half* __restrict__ gBh, const __half* __restrict__ gBl,
    int K, uint32_t smem_base, float acc[4][8][4])
{
    constexpr uint32_t TB = 8192u;
    constexpr uint32_t STAGE_B = 3 * TB;
    constexpr uint32_t T_AH = 0, T_BH = TB, T_BL = 2 * TB;

    const int tid = threadIdx.x;
    const int lane = tid & 31;
    const int w = tid >> 5;
    const int wm = w >> 1, wn = w & 1;

    const int ld_row = tid >> 2;          // 0..31 (+32 per iter, 4 iters)
    const int ld_u   = tid & 3;

    const int a_row0 = wm * 64 + (lane & 15);
    const int a_uadd = lane >> 4;
    const int b_row0 = wn * 64 + (lane & 7) + ((lane >> 4) << 3);
    const int b_uadd = (lane >> 3) & 1;

    auto load_chunk = [&](int c) {
        const uint32_t sb = smem_base + (uint32_t)(c % STAGES) * STAGE_B;
        const long long koff = (long long)c * 32;
        const __half* gp[3] = { gAh + koff, gBh + koff, gBl + koff };
#pragma unroll
        for (int t = 0; t < 3; ++t) {
#pragma unroll
            for (int i = 0; i < 4; ++i) {
                const int row = ld_row + i * 32;
                const void* g = gp[t] + (long long)row * K + ld_u * 8;
                CP_ASYNC16(sb + t * TB + foff<32>(row, ld_u), g);
            }
        }
        CP_COMMIT();
    };

    const int nCh = K >> 5;
#pragma unroll 1
    for (int c = 0; c < STAGES; ++c) load_chunk(c);

#pragma unroll 1
    for (int c = 0; c < nCh; ++c) {
        CP_WAIT(STAGES - 1);
        __syncthreads();
        const uint32_t sb = smem_base + (uint32_t)(c % STAGES) * STAGE_B;

#pragma unroll
        for (int ks = 0; ks < 2; ++ks) {
            uint32_t aF[4][4], bF[8][2];
            // A fragments for this ks (shared by both terms)
#pragma unroll
            for (int mf = 0; mf < 4; ++mf)
                ldsm4(aF[mf], sb + T_AH + foff<32>(a_row0 + mf * 16, ks * 2 + a_uadd));
            // term 1: B hi
#pragma unroll
            for (int nh = 0; nh < 4; ++nh) {
                uint32_t r4[4];
                ldsm4(r4, sb + T_BH + foff<32>(b_row0 + nh * 16, ks * 2 + b_uadd));
                bF[2 * nh][0] = r4[0]; bF[2 * nh][1] = r4[1];
                bF[2 * nh + 1][0] = r4[2]; bF[2 * nh + 1][1] = r4[3];
            }
#pragma unroll
            for (int mf = 0; mf < 4; ++mf)
#pragma unroll
                for (int nf = 0; nf < 8; ++nf)
                    mma16816(acc[mf][nf], aF[mf], bF[nf]);
            // term 2: B lo (reuse bF registers)
#pragma unroll
            for (int nh = 0; nh < 4; ++nh) {
                uint32_t r4[4];
                ldsm4(r4, sb + T_BL + foff<32>(b_row0 + nh * 16, ks * 2 + b_uadd));
                bF[2 * nh][0] = r4[0]; bF[2 * nh][1] = r4[1];
                bF[2 * nh + 1][0] = r4[2]; bF[2 * nh + 1][1] = r4[3];
            }
#pragma unroll
            for (int mf = 0; mf < 4; ++mf)
#pragma unroll
                for (int nf = 0; nf < 8; ++nf)
                    mma16816(acc[mf][nf], aF[mf], bF[nf]);
        }

        __syncthreads();
        if (c + STAGES < nCh) load_chunk(c + STAGES);
        else CP_COMMIT();
    }
}

// ---------------------------------------------------------------------------
// 2-term GEMM kernel (out-proj): fp32 + bias epilogue, 64x64 warp tiles
// ---------------------------------------------------------------------------
__global__ void __launch_bounds__(128, 3)
mma_gemm2_bias(const __half* __restrict__ Ah, const __half* __restrict__ Bh,
               const __half* __restrict__ Bl, float* __restrict__ Cf,
               const float* __restrict__ bias, int K, int ldC)
{
    extern __shared__ __align__(1024) char smem[];
    const uint32_t smem_base = smem_u32_of(smem);

    const int tid = threadIdx.x;
    const int lane = tid & 31;
    const int w = tid >> 5;
    const int wm = w >> 1, wn = w & 1;
    const int bm = blockIdx.y * 128;
    const int bn = blockIdx.x * 128;

    float acc[4][8][4] = {};
    gemm2_core(Ah + (long long)bm * K,
               Bh + (long long)bn * K, Bl + (long long)bn * K,
               K, smem_base, acc);

    const int g = lane >> 2, tig = lane & 3;
#pragma unroll
    for (int mf = 0; mf < 4; ++mf) {
#pragma unroll
        for (int h2 = 0; h2 < 2; ++h2) {
            const int row = bm + wm * 64 + mf * 16 + g + h2 * 8;
#pragma unroll
            for (int nf = 0; nf < 8; ++nf) {
                const int col = bn + wn * 64 + nf * 8 + 2 * tig;
                *(float2*)(Cf + (long long)row * ldC + col) =
                    make_float2(acc[mf][nf][h2 * 2 + 0] + bias[col],
                                acc[mf][nf][h2 * 2 + 1] + bias[col + 1]);
            }
        }
    }
}

// ---------------------------------------------------------------------------
// Merged Q/K/V projection kernel (2-term, 64x64 warp tiles).
// z=0 (Q), z=1 (K): write hi.  z=2 (V): write hi transposed.
// ---------------------------------------------------------------------------
struct Ptrs3 {
    const __half *Ah, *Bh, *Bl;
    __half *Oh;
};
struct QKVArgs { Ptrs3 p[3]; };

__global__ void __launch_bounds__(128, 3)
qkv_gemm(QKVArgs args)
{
    extern __shared__ __align__(1024) char smem[];
    const uint32_t smem_base = smem_u32_of(smem);

    const int tid = threadIdx.x;
    const int lane = tid & 31;
    const int w = tid >> 5;
    const int wm = w >> 1, wn = w & 1;
    const int z = blockIdx.z;
    const int bm = blockIdx.y * 128;
    const int bn = blockIdx.x * 128;
    const Ptrs3 pp = args.p[z];

    float acc[4][8][4] = {};
    gemm2_core(pp.Ah + (long long)bm * EMB,
               pp.Bh + (long long)bn * EMB, pp.Bl + (long long)bn * EMB,
               EMB, smem_base, acc);

    const int g = lane >> 2, tig = lane & 3;
    const bool doT = (z == 2);
#pragma unroll
    for (int mf = 0; mf < 4; ++mf) {
#pragma unroll
        for (int h2 = 0; h2 < 2; ++h2) {
            const int row = bm + wm * 64 + mf * 16 + g + h2 * 8;
#pragma unroll
            for (int nf = 0; nf < 8; ++nf) {
                const int col = bn + wn * 64 + nf * 8 + 2 * tig;
                const float x0 = acc[mf][nf][h2 * 2 + 0];
                const float x1 = acc[mf][nf][h2 * 2 + 1];
                __half hh0 = __float2half(x0), hh1 = __float2half(x1);
                if (!doT) {
                    *(uint32_t*)(pp.Oh + (long long)row * EMB + col) = packh2(hh0, hh1);
                } else {  // V: transposed hi, dest [b][d=col][l=row&4095]
                    const int b = row >> 12, l = row & 4095;
                    const long long ib = (long long)b * (EMB * SEQ) + l;
                    pp.Oh[ib + (long long)col * SEQ] = hh0;
                    pp.Oh[ib + (long long)(col + 1) * SEQ] = hh1;
                }
            }
        }
    }
}

// ---------------------------------------------------------------------------
// Merged fp32 -> fp16 conversion: segs 0-2 (inputs) hi only; 3-6 (weights) hi+lo
// ---------------------------------------------------------------------------
struct CvtArgs {
    const float4* x[7];
    uint2* h[7];
    uint2* l[7];
};
#define BIG4  (NTOK * EMB / 4)   // 2097152
#define W4    (EMB * EMB / 4)    // 65536
#define CVT_TOT (3 * BIG4 + 4 * W4)

__global__ void cvt_all(CvtArgs args)
{
    int idx = blockIdx.x * 256 + threadIdx.x;
    if (idx >= CVT_TOT) return;
    int seg, off;
    if (idx < 3 * BIG4) { seg = idx / BIG4; off = idx - seg * BIG4; }
    else { int j = idx - 3 * BIG4; seg = 3 + j / W4; off = j & (W4 - 1); }
    float4 v = args.x[seg][off];
    __half h0 = __float2half(v.x), h1 = __float2half(v.y);
    __half h2 = __float2half(v.z), h3 = __float2half(v.w);
    args.h[seg][off] = make_uint2(packh2(h0, h1), packh2(h2, h3));
    if (seg >= 3) {
        __half l0 = __float2half(v.x - __half2float(h0));
        __half l1 = __float2half(v.y - __half2float(h1));
        __half l2 = __float2half(v.z - __half2float(h2));
        __half l3 = __float2half(v.w - __half2float(h3));
        args.l[seg][off] = make_uint2(packh2(l0, l1), packh2(l2, l3));
    }
}

// ---------------------------------------------------------------------------
// softmax over scaled fp16 energy with RAW int32 mask; writes fp16 attn
// ---------------------------------------------------------------------------
__global__ void softmax_kernel(const __half* __restrict__ Eh,
                               const int* __restrict__ mask,
                               __half* __restrict__ Ph)
{
    const long long row = blockIdx.x;
    const uint4* e8 = (const uint4*)(Eh + row * (long long)SEQ);
    const int4* m4 = (const int4*)(mask + row * (long long)SEQ);
    uint4* p8 = (uint4*)(Ph + row * (long long)SEQ);
    const int tid = threadIdx.x;

    float v[16];
    float lmax = -3.0e38f;
#pragma unroll
    for (int i = 0; i < 2; ++i) {
        const int gi = tid + (i << 8);
        const uint4 ev = e8[gi];
        const int4 m0 = m4[2 * gi];
        const int4 m1 = m4[2 * gi + 1];
        const uint32_t ew[4] = {ev.x, ev.y, ev.z, ev.w};
        const int mm[8] = {m0.x, m0.y, m0.z, m0.w, m1.x, m1.y, m1.z, m1.w};
#pragma unroll
        for (int j = 0; j < 4; ++j) {
            const float2 f2 = __half22float2(*(const __half2*)&ew[j]);
            const float a = (mm[2 * j] != 0) ? f2.x : -1.0e20f;
            const float b = (mm[2 * j + 1] != 0) ? f2.y : -1.0e20f;
            v[8 * i + 2 * j] = a;
            v[8 * i + 2 * j + 1] = b;
            lmax = fmaxf(lmax, fmaxf(a, b));
        }
    }

    __shared__ float red[8];
#pragma unroll
    for (int o = 16; o > 0; o >>= 1)
        lmax = fmaxf(lmax, __shfl_xor_sync(0xffffffffu, lmax, o));
    if ((tid & 31) == 0) red[tid >> 5] = lmax;
    __syncthreads();
    float rowmax = red[0];
#pragma unroll
    for (int wv = 1; wv < 8; ++wv) rowmax = fmaxf(rowmax, red[wv]);
    __syncthreads();

    float lsum = 0.f;
#pragma unroll
    for (int i = 0; i < 16; ++i) {
        v[i] = __expf(v[i] - rowmax);
        lsum += v[i];
    }
#pragma unroll
    for (int o = 16; o > 0; o >>= 1)
        lsum += __shfl_xor_sync(0xffffffffu, lsum, o);
    if ((tid & 31) == 0) red[tid >> 5] = lsum;
    __syncthreads();
    float rowsum = 0.f;
#pragma unroll
    for (int wv = 0; wv < 8; ++wv) rowsum += red[wv];
    const float inv = 1.0f / rowsum;

#pragma unroll
    for (int i = 0; i < 2; ++i) {
        const int gi = tid + (i << 8);
        uint4 o;
        o.x = packh2(__float2half(v[8*i+0] * inv), __float2half(v[8*i+1] * inv));
        o.y = packh2(__float2half(v[8*i+2] * inv), __float2half(v[8*i+3] * inv));
        o.z = packh2(__float2half(v[8*i+4] * inv), __float2half(v[8*i+5] * inv));
        o.w = packh2(__float2half(v[8*i+6] * inv), __float2half(v[8*i+7] * inv));
        p8[gi] = o;
    }
}

// ---------------------------------------------------------------------------
// Launch
// ---------------------------------------------------------------------------
extern "C" void kernel_launch(void* const* d_in, const int* in_sizes, int n_in,
                              void* d_out, int out_size)
{
    (void)in_sizes; (void)n_in; (void)out_size;

    const float* values = (const float*)d_in[0];
    const float* keys   = (const float*)d_in[1];
    const float* query  = (const float*)d_in[2];
    const int*   mask   = (const int*)  d_in[3];
    const float* Wv     = (const float*)d_in[4];
    const float* Wk     = (const float*)d_in[5];
    const float* Wq     = (const float*)d_in[6];
    const float* Wo     = (const float*)d_in[7];
    const float* bo     = (const float*)d_in[8];
    float* out = (float*)d_out;

    __half *vh, *kh, *qh;
    __half *Wvh, *Wvl, *Wkh, *Wkl, *Wqh, *Wql, *Woh, *Wol;
    __half *Qph, *Kph, *VTh, *Eh, *Ph, *AOh;
    cudaGetSymbolAddress((void**)&vh, g_vh);
    cudaGetSymbolAddress((void**)&kh, g_kh);
    cudaGetSymbolAddress((void**)&qh, g_qh);
    cudaGetSymbolAddress((void**)&Wvh, g_Wvh); cudaGetSymbolAddress((void**)&Wvl, g_Wvl);
    cudaGetSymbolAddress((void**)&Wkh, g_Wkh); cudaGetSymbolAddress((void**)&Wkl, g_Wkl);
    cudaGetSymbolAddress((void**)&Wqh, g_Wqh); cudaGetSymbolAddress((void**)&Wql, g_Wql);
    cudaGetSymbolAddress((void**)&Woh, g_Woh); cudaGetSymbolAddress((void**)&Wol, g_Wol);
    cudaGetSymbolAddress((void**)&Qph, g_Qph);
    cudaGetSymbolAddress((void**)&Kph, g_Kph);
    cudaGetSymbolAddress((void**)&VTh, g_VTh);
    cudaGetSymbolAddress((void**)&Eh, g_Eh);
    cudaGetSymbolAddress((void**)&Ph, g_Ph);
    cudaGetSymbolAddress((void**)&AOh, g_AOh);

    constexpr int SM1_64 = STAGES1 * 2 * 16384;  // 64 KB (1-term, chunk 64, 2 stages)
    constexpr int SM2_32 = STAGES * 3 * 8192;    // 72 KB (2-term, chunk 32, 3 stages)
    cudaFuncSetAttribute((const void*)mma_gemm1<2>, cudaFuncAttributeMaxDynamicSharedMemorySize, SM1_64);
    cudaFuncSetAttribute((const void*)mma_gemm1<4>, cudaFuncAttributeMaxDynamicSharedMemorySize, SM1_64);
    cudaFuncSetAttribute((const void*)mma_gemm2_bias, cudaFuncAttributeMaxDynamicSharedMemorySize, SM2_32);
    cudaFuncSetAttribute((const void*)qkv_gemm, cudaFuncAttributeMaxDynamicSharedMemorySize, SM2_32);

    // 1) convert: inputs -> hi fp16; weights -> hi/lo fp16
    CvtArgs ca;
    ca.x[0] = (const float4*)query;  ca.h[0] = (uint2*)qh;  ca.l[0] = nullptr;
    ca.x[1] = (const float4*)keys;   ca.h[1] = (uint2*)kh;  ca.l[1] = nullptr;
    ca.x[2] = (const float4*)values; ca.h[2] = (uint2*)vh;  ca.l[2] = nullptr;
    ca.x[3] = (const float4*)Wq;     ca.h[3] = (uint2*)Wqh; ca.l[3] = (uint2*)Wql;
    ca.x[4] = (const float4*)Wk;     ca.h[4] = (uint2*)Wkh; ca.l[4] = (uint2*)Wkl;
    ca.x[5] = (const float4*)Wv;     ca.h[5] = (uint2*)Wvh; ca.l[5] = (uint2*)Wvl;
    ca.x[6] = (const float4*)Wo;     ca.h[6] = (uint2*)Woh; ca.l[6] = (uint2*)Wol;
    cvt_all<<<(CVT_TOT + 255) / 256, 256>>>(ca);

    const long long sQK = (long long)SEQ * EMB;
    const long long sE  = (long long)SEQ * SEQ;

    // 2) merged projections (2-term, 64x64 warp tiles)
    QKVArgs qa;
    qa.p[0] = { qh, Wqh, Wql, Qph };
    qa.p[1] = { kh, Wkh, Wkl, Kph };
    qa.p[2] = { vh, Wvh, Wvl, VTh };
    qkv_gemm<<<dim3(EMB / 128, NTOK / 128, 3), 128, SM2_32>>>(qa);

    // 3) energy: Qph @ Kph^T -> scaled fp16
    mma_gemm1<2><<<dim3(SEQ / 128, SEQ / 128, NB), 128, SM1_64>>>(
        Qph, Kph, Eh, EMB, SEQ, sQK, sQK, sE);

    // 4) softmax with raw int32 mask -> attn fp16 (hi only)
    softmax_kernel<<<NB * SEQ, 256>>>(Eh, mask, Ph);

    // 5) attn @ V: Ph @ VTh^T (hi out)
    mma_gemm1<4><<<dim3(EMB / 128, SEQ / 128, NB), 128, SM1_64>>>(
        Ph, VTh, AOh, SEQ, EMB, sE, sQK, sQK);

    // 6) output projection + bias, 2-term (fp32 out)
    mma_gemm2_bias<<<dim3(EMB / 128, NTOK / 128, 1), 128, SM2_32>>>(
        AOh, Woh, Wol, out, bo, EMB, EMB);
}

// round 17
// speedup vs baseline: 1.0983x; 1.0983x over previous
#include <cuda_runtime.h>
#include <cuda_fp16.h>
#include <cstdint>

#define NB   4
#define SEQ  4096
#define EMB  512
#define NTOK (NB * SEQ)   // 16384

// ---------------------------------------------------------------------------
// Device scratch
// ---------------------------------------------------------------------------
__device__ __half g_vh[(size_t)NTOK * EMB];
__device__ __half g_kh[(size_t)NTOK * EMB];
__device__ __half g_qh[(size_t)NTOK * EMB];
__device__ __half g_Wvh[EMB * EMB], g_Wvl[EMB * EMB];
__device__ __half g_Wkh[EMB * EMB], g_Wkl[EMB * EMB];
__device__ __half g_Wqh[EMB * EMB], g_Wql[EMB * EMB];
__device__ __half g_Woh[EMB * EMB], g_Wol[EMB * EMB];
__device__ __half g_Qph[(size_t)NTOK * EMB];                        // hi only
__device__ __half g_Kph[(size_t)NTOK * EMB];                        // hi only
__device__ __half g_VTh[(size_t)NTOK * EMB];                        // hi only, [b][d][l]
__device__ __half g_Eh [(size_t)NB * SEQ * SEQ];                    // scaled fp16 energy
__device__ __half g_Ph [(size_t)NB * SEQ * SEQ];                    // hi only
__device__ __half g_AOh[(size_t)NTOK * EMB];                        // hi only

// ---------------------------------------------------------------------------
// helpers
// ---------------------------------------------------------------------------
__device__ __forceinline__ uint32_t smem_u32_of(const void* p) {
    uint32_t a;
    asm("{ .reg .u64 t; cvta.to.shared.u64 t, %1; cvt.u32.u64 %0, t; }" : "=r"(a) : "l"(p));
    return a;
}

__device__ __forceinline__ void ldsm4(uint32_t* r, uint32_t addr) {
    asm volatile("ldmatrix.sync.aligned.m8n8.x4.shared.b16 {%0,%1,%2,%3}, [%4];"
                 : "=r"(r[0]), "=r"(r[1]), "=r"(r[2]), "=r"(r[3]) : "r"(addr));
}

__device__ __forceinline__ void mma16816(float* c, const uint32_t* a, const uint32_t* b) {
    asm volatile(
        "mma.sync.aligned.m16n8k16.row.col.f32.f16.f16.f32 "
        "{%0,%1,%2,%3}, {%4,%5,%6,%7}, {%8,%9}, {%0,%1,%2,%3};"
        : "+f"(c[0]), "+f"(c[1]), "+f"(c[2]), "+f"(c[3])
        : "r"(a[0]), "r"(a[1]), "r"(a[2]), "r"(a[3]), "r"(b[0]), "r"(b[1]));
}

#define CP_ASYNC16(dst, src) \
    asm volatile("cp.async.cg.shared.global [%0], [%1], 16;" :: "r"(dst), "l"(src))
#define CP_COMMIT() asm volatile("cp.async.commit_group;")
#define CP_WAIT(n)  asm volatile("cp.async.wait_group %0;" :: "n"(n))

__device__ __forceinline__ uint32_t packh2(__half a, __half b) {
    __half2 h = __halves2half2(a, b);
    return *(uint32_t*)&h;
}

#define STAGES 3
#define STAGES1 2
#define SOFT_SCALE 0.044194173824159216f   // 1/sqrt(512)

// smem offset helpers
// CHUNK=32: packed 2-rows-per-128B (tile 128 x 32 halves = 8 KB), u in 0..3
// CHUNK=64: plain 128B rows        (tile 128 x 64 halves = 16 KB), u in 0..7
template <int CHUNK>
__device__ __forceinline__ uint32_t foff(int row, int u) {
    uint32_t off;
    if (CHUNK == 64) off = (uint32_t)(row * 128 + u * 16);
    else             off = (uint32_t)(((row >> 1) << 7) | ((row & 1) << 6) | (u << 4));
    return off ^ ((off >> 3) & 0x70);
}

// ---------------------------------------------------------------------------
// 1-term GEMM kernel: 128 threads, warp tile 64x64 (2x2), CTA tile 128x128,
// chunk 64, 2 smem stages, occupancy 3.  (R14 form, unchanged)
// EPI: 2 = scaled fp16 (energy); 4 = fp16 hi only
// ---------------------------------------------------------------------------
template <int EPI>
__global__ void __launch_bounds__(128, 3)
mma_gemm1(const __half* __restrict__ Ah, const __half* __restrict__ Bh,
          __half* __restrict__ Coh,
          int K, int ldC, long long sA, long long sB, long long sC)
{
    extern __shared__ __align__(1024) char smem[];
    const uint32_t smem_base = smem_u32_of(smem);
    constexpr uint32_t TB = 16384u;
    constexpr uint32_t STAGE_B = 2 * TB;

    const int tid = threadIdx.x;
    const int lane = tid & 31;
    const int w = tid >> 5;
    const int wm = w >> 1, wn = w & 1;
    const int z = blockIdx.z;
    const int bm = blockIdx.y * 128;
    const int bn = blockIdx.x * 128;

    const __half* gAh = Ah + (long long)z * sA + (long long)bm * K;
    const __half* gBh = Bh + (long long)z * sB + (long long)bn * K;

    const int ld_row = tid >> 3;
    const int ld_u   = tid & 7;

    const int a_row0 = wm * 64 + (lane & 15);
    const int a_uadd = lane >> 4;
    const int b_row0 = wn * 64 + (lane & 7) + ((lane >> 4) << 3);
    const int b_uadd = (lane >> 3) & 1;

    auto load_chunk = [&](int c) {
        const uint32_t sb = smem_base + (uint32_t)(c % STAGES1) * STAGE_B;
        const long long koff = (long long)c * 64;
        const __half* gp[2] = { gAh + koff, gBh + koff };
#pragma unroll
        for (int t = 0; t < 2; ++t) {
#pragma unroll
            for (int i = 0; i < 8; ++i) {
                const int row = ld_row + i * 16;
                const void* g = gp[t] + (long long)row * K + ld_u * 8;
                CP_ASYNC16(sb + t * TB + foff<64>(row, ld_u), g);
            }
        }
        CP_COMMIT();
    };

    float acc[4][8][4] = {};

    const int nCh = K >> 6;
#pragma unroll 1
    for (int c = 0; c < STAGES1; ++c) load_chunk(c);

#pragma unroll 1
    for (int c = 0; c < nCh; ++c) {
        CP_WAIT(STAGES1 - 1);
        __syncthreads();
        const uint32_t sb = smem_base + (uint32_t)(c % STAGES1) * STAGE_B;

#pragma unroll
        for (int ks = 0; ks < 4; ++ks) {
            uint32_t bF[8][2];
#pragma unroll
            for (int nh = 0; nh < 4; ++nh) {
                uint32_t r4[4];
                ldsm4(r4, sb + TB + foff<64>(b_row0 + nh * 16, ks * 2 + b_uadd));
                bF[2 * nh][0] = r4[0]; bF[2 * nh][1] = r4[1];
                bF[2 * nh + 1][0] = r4[2]; bF[2 * nh + 1][1] = r4[3];
            }
#pragma unroll
            for (int mf = 0; mf < 4; ++mf) {
                uint32_t aF[4];
                ldsm4(aF, sb + foff<64>(a_row0 + mf * 16, ks * 2 + a_uadd));
#pragma unroll
                for (int nf = 0; nf < 8; ++nf)
                    mma16816(acc[mf][nf], aF, bF[nf]);
            }
        }

        __syncthreads();
        if (c + STAGES1 < nCh) load_chunk(c + STAGES1);
        else CP_COMMIT();
    }

    // epilogue: warp tile 64x64
    const int g = lane >> 2, tig = lane & 3;
#pragma unroll
    for (int mf = 0; mf < 4; ++mf) {
#pragma unroll
        for (int h2 = 0; h2 < 2; ++h2) {
            const int row = bm + wm * 64 + mf * 16 + g + h2 * 8;
#pragma unroll
            for (int nf = 0; nf < 8; ++nf) {
                const int col = bn + wn * 64 + nf * 8 + 2 * tig;
                const float x0 = acc[mf][nf][h2 * 2 + 0];
                const float x1 = acc[mf][nf][h2 * 2 + 1];
                const long long base = (long long)z * sC + (long long)row * ldC + col;
                if (EPI == 2) {
                    *(uint32_t*)(Coh + base) =
                        packh2(__float2half(x0 * SOFT_SCALE), __float2half(x1 * SOFT_SCALE));
                } else {
                    *(uint32_t*)(Coh + base) = packh2(__float2half(x0), __float2half(x1));
                }
            }
        }
    }
}

// ---------------------------------------------------------------------------
// NEW: 1-term GEMM, CTA tile 128x64 (AV wave balance).  128 threads, warp
// tile 64x32 (2x2 grid), chunk 64, 2 stages (24 KB each), occupancy 4.
// fp16 hi epilogue.
// ---------------------------------------------------------------------------
__global__ void __launch_bounds__(128, 4)
mma_gemm1_n64(const __half* __restrict__ Ah, const __half* __restrict__ Bh,
              __half* __restrict__ Coh,
              int K, int ldC, long long sA, long long sB, long long sC)
{
    extern __shared__ __align__(1024) char smem[];
    const uint32_t smem_base = smem_u32_of(smem);
    constexpr uint32_t TA = 16384u;          // A tile: 128 rows x 128B
    constexpr uint32_t TBB = 8192u;          // B tile: 64 rows x 128B
    constexpr uint32_t STAGE_B = TA + TBB;   // 24 KB

    const int tid = threadIdx.x;
    const int lane = tid & 31;
    const int w = tid >> 5;
    const int wm = w >> 1, wn = w & 1;       // 2x2 warp grid, warp tile 64x32
    const int z = blockIdx.z;
    const int bm = blockIdx.y * 128;
    const int bn = blockIdx.x * 64;

    const __half* gAh = Ah + (long long)z * sA + (long long)bm * K;
    const __half* gBh = Bh + (long long)z * sB + (long long)bn * K;

    const int ld_row = tid >> 3;             // 0..15
    const int ld_u   = tid & 7;

    const int a_row0 = wm * 64 + (lane & 15);
    const int a_uadd = lane >> 4;
    const int b_row0 = wn * 32 + (lane & 7) + ((lane >> 4) << 3);
    const int b_uadd = (lane >> 3) & 1;

    auto load_chunk = [&](int c) {
        const uint32_t sb = smem_base + (uint32_t)(c & 1) * STAGE_B;
        const long long koff = (long long)c * 64;
        // A: 1024 vec16 -> 8 iters of 128 threads
#pragma unroll
        for (int i = 0; i < 8; ++i) {
            const int row = ld_row + i * 16;
            const void* g = gAh + koff + (long long)row * K + ld_u * 8;
            CP_ASYNC16(sb + foff<64>(row, ld_u), g);
        }
        // B: 512 vec16 -> 4 iters
#pragma unroll
        for (int i = 0; i < 4; ++i) {
            const int row = ld_row + i * 16;
            const void* g = gBh + koff + (long long)row * K + ld_u * 8;
            CP_ASYNC16(sb + TA + foff<64>(row, ld_u), g);
        }
        CP_COMMIT();
    };

    float acc[4][4][4] = {};

    const int nCh = K >> 6;
#pragma unroll 1
    for (int c = 0; c < 2; ++c) load_chunk(c);

#pragma unroll 1
    for (int c = 0; c < nCh; ++c) {
        CP_WAIT(1);
        __syncthreads();
        const uint32_t sb = smem_base + (uint32_t)(c & 1) * STAGE_B;

#pragma unroll
        for (int ks = 0; ks < 4; ++ks) {
            uint32_t bF[4][2];
#pragma unroll
            for (int nh = 0; nh < 2; ++nh) {
                uint32_t r4[4];
                ldsm4(r4, sb + TA + foff<64>(b_row0 + nh * 16, ks * 2 + b_uadd));
                bF[2 * nh][0] = r4[0]; bF[2 * nh][1] = r4[1];
                bF[2 * nh + 1][0] = r4[2]; bF[2 * nh + 1][1] = r4[3];
            }
#pragma unroll
            for (int mf = 0; mf < 4; ++mf) {
                uint32_t aF[4];
                ldsm4(aF, sb + foff<64>(a_row0 + mf * 16, ks * 2 + a_uadd));
#pragma unroll
                for (int nf = 0; nf < 4; ++nf)
                    mma16816(acc[mf][nf], aF, bF[nf]);
            }
        }

        __syncthreads();
        if (c + 2 < nCh) load_chunk(c + 2);
        else CP_COMMIT();
    }

    // epilogue: warp tile 64x32, fp16 hi
    const int g = lane >> 2, tig = lane & 3;
#pragma unroll
    for (int mf = 0; mf < 4; ++mf) {
#pragma unroll
        for (int h2 = 0; h2 < 2; ++h2) {
            const int row = bm + wm * 64 + mf * 16 + g + h2 * 8;
#pragma unroll
            for (int nf = 0; nf < 4; ++nf) {
                const int col = bn + wn * 32 + nf * 8 + 2 * tig;
                const long long base = (long long)z * sC + (long long)row * ldC + col;
                *(uint32_t*)(Coh + base) =
                    packh2(__float2half(acc[mf][nf][h2 * 2 + 0]),
                           __float2half(acc[mf][nf][h2 * 2 + 1]));
            }
        }
    }
}

// ---------------------------------------------------------------------------
// Multi-term GEMM core (TERMS 2, chunk 32, 3 stages) — R14 form, unchanged.
// ---------------------------------------------------------------------------
template <int TERMS, int CHUNK>
__device__ __forceinline__ void gemm_core(
    const __half* __restrict__ gAh, const __half* __restrict__ gAl,
    const __half* __restrict__ gBh, const __half* __restrict__ gBl,
    int K, uint32_t smem_base, float acc[4][4][4])
{
    constexpr int A2 = (TERMS == 3) ? 1 : 0;
    constexpr int B2 = (TERMS >= 2) ? 1 : 0;
    constexpr int NT = 2 + A2 + B2;
    constexpr uint32_t TB = (CHUNK == 64) ? 16384u : 8192u;
    constexpr uint32_t STAGE_B = NT * TB;
    constexpr uint32_t T_AH = 0;
    constexpr uint32_t T_AL = TB;
    constexpr uint32_t T_BH = (1 + A2) * TB;
    constexpr uint32_t T_BL = (2 + A2) * TB;
    constexpr int KS_N = CHUNK / 16;

    const int tid = threadIdx.x;
    const int lane = tid & 31;
    const int w = tid >> 5;
    const int wm = w >> 2, wn = w & 3;

    const int ld_row = (CHUNK == 64) ? (tid >> 3) : (tid >> 2);
    const int ld_u   = (CHUNK == 64) ? (tid & 7) : (tid & 3);
    constexpr int LD_IT   = (CHUNK == 64) ? 4 : 2;
    constexpr int LD_STEP = (CHUNK == 64) ? 32 : 64;

    const int a_row0 = wm * 64 + (lane & 15);
    const int a_uadd = lane >> 4;
    const int b_row0 = wn * 32 + (lane & 7) + ((lane >> 4) << 3);
    const int b_uadd = (lane >> 3) & 1;

    auto load_chunk = [&](int c) {
        const uint32_t sb = smem_base + (uint32_t)(c % STAGES) * STAGE_B;
        const long long koff = (long long)c * CHUNK;
        const __half* gp[NT];
        gp[0] = gAh + koff;
        if (A2) gp[1] = gAl + koff;
        gp[1 + A2] = gBh + koff;
        if (B2) gp[2 + A2] = gBl + koff;
#pragma unroll
        for (int t = 0; t < NT; ++t) {
#pragma unroll
            for (int i = 0; i < LD_IT; ++i) {
                const int row = ld_row + i * LD_STEP;
                const void* g = gp[t] + (long long)row * K + ld_u * 8;
                CP_ASYNC16(sb + t * TB + foff<CHUNK>(row, ld_u), g);
            }
        }
        CP_COMMIT();
    };

    const int nCh = K / CHUNK;
#pragma unroll 1
    for (int c = 0; c < STAGES; ++c) load_chunk(c);

#pragma unroll 1
    for (int c = 0; c < nCh; ++c) {
        CP_WAIT(STAGES - 1);
        __syncthreads();
        const uint32_t sb = smem_base + (uint32_t)(c % STAGES) * STAGE_B;

#pragma unroll
        for (int ks = 0; ks < KS_N; ++ks) {
            uint32_t bH[4][2], bL[4][2];
#pragma unroll
            for (int nh = 0; nh < 2; ++nh) {
                const uint32_t off = foff<CHUNK>(b_row0 + nh * 16, ks * 2 + b_uadd);
                uint32_t r4[4];
                ldsm4(r4, sb + T_BH + off);
                bH[2 * nh][0] = r4[0]; bH[2 * nh][1] = r4[1];
                bH[2 * nh + 1][0] = r4[2]; bH[2 * nh + 1][1] = r4[3];
                if (B2) {
                    ldsm4(r4, sb + T_BL + off);
                    bL[2 * nh][0] = r4[0]; bL[2 * nh][1] = r4[1];
                    bL[2 * nh + 1][0] = r4[2]; bL[2 * nh + 1][1] = r4[3];
                }
            }
#pragma unroll
            for (int mf = 0; mf < 4; ++mf) {
                const uint32_t off = foff<CHUNK>(a_row0 + mf * 16, ks * 2 + a_uadd);
                uint32_t aH[4], aL[4];
                ldsm4(aH, sb + T_AH + off);
                if (A2) ldsm4(aL, sb + T_AL + off);
#pragma unroll
                for (int nf = 0; nf < 4; ++nf) {
                    mma16816(acc[mf][nf], aH, bH[nf]);
                    if (B2) mma16816(acc[mf][nf], aH, bL[nf]);
                    if (A2) mma16816(acc[mf][nf], aL, bH[nf]);
                }
            }
        }

        __syncthreads();
        if (c + STAGES < nCh) load_chunk(c + STAGES);
        else CP_COMMIT();
    }
}

// ---------------------------------------------------------------------------
// 2-term GEMM kernel (out-proj).  fp32 + bias epilogue  (R14 form)
// ---------------------------------------------------------------------------
__global__ void __launch_bounds__(256, 2)
mma_gemm2_bias(const __half* __restrict__ Ah, const __half* __restrict__ Bh,
               const __half* __restrict__ Bl, float* __restrict__ Cf,
               const float* __restrict__ bias, int K, int ldC)
{
    extern __shared__ __align__(1024) char smem[];
    const uint32_t smem_base = smem_u32_of(smem);

    const int tid = threadIdx.x;
    const int lane = tid & 31;
    const int w = tid >> 5;
    const int wm = w >> 2, wn = w & 3;
    const int bm = blockIdx.y * 128;
    const int bn = blockIdx.x * 128;

    float acc[4][4][4] = {};
    gemm_core<2, 32>(Ah + (long long)bm * K, nullptr,
                     Bh + (long long)bn * K, Bl + (long long)bn * K,
                     K, smem_base, acc);

    const int g = lane >> 2, tig = lane & 3;
#pragma unroll
    for (int mf = 0; mf < 4; ++mf) {
#pragma unroll
        for (int h2 = 0; h2 < 2; ++h2) {
            const int row = bm + wm * 64 + mf * 16 + g + h2 * 8;
#pragma unroll
            for (int nf = 0; nf < 4; ++nf) {
                const int col = bn + wn * 32 + nf * 8 + 2 * tig;
                *(float2*)(Cf + (long long)row * ldC + col) =
                    make_float2(acc[mf][nf][h2 * 2 + 0] + bias[col],
                                acc[mf][nf][h2 * 2 + 1] + bias[col + 1]);
            }
        }
    }
}

// ---------------------------------------------------------------------------
// Merged Q/K/V projection kernel (2-term: XhWh + XhWl, chunk 32). (R14 form)
// ---------------------------------------------------------------------------
struct Ptrs3 {
    const __half *Ah, *Bh, *Bl;
    __half *Oh;
};
struct QKVArgs { Ptrs3 p[3]; };

__global__ void __launch_bounds__(256, 2)
qkv_gemm(QKVArgs args)
{
    extern __shared__ __align__(1024) char smem[];
    const uint32_t smem_base = smem_u32_of(smem);

    const int tid = threadIdx.x;
    const int lane = tid & 31;
    const int w = tid >> 5;
    const int wm = w >> 2, wn = w & 3;
    const int z = blockIdx.z;
    const int bm = blockIdx.y * 128;
    const int bn = blockIdx.x * 128;
    const Ptrs3 pp = args.p[z];

    float acc[4][4][4] = {};
    gemm_core<2, 32>(pp.Ah + (long long)bm * EMB, nullptr,
                     pp.Bh + (long long)bn * EMB, pp.Bl + (long long)bn * EMB,
                     EMB, smem_base, acc);

    const int g = lane >> 2, tig = lane & 3;
    const bool doT = (z == 2);
#pragma unroll
    for (int mf = 0; mf < 4; ++mf) {
#pragma unroll
        for (int h2 = 0; h2 < 2; ++h2) {
            const int row = bm + wm * 64 + mf * 16 + g + h2 * 8;
#pragma unroll
            for (int nf = 0; nf < 4; ++nf) {
                const int col = bn + wn * 32 + nf * 8 + 2 * tig;
                const float x0 = acc[mf][nf][h2 * 2 + 0];
                const float x1 = acc[mf][nf][h2 * 2 + 1];
                __half hh0 = __float2half(x0), hh1 = __float2half(x1);
                if (!doT) {
                    *(uint32_t*)(pp.Oh + (long long)row * EMB + col) = packh2(hh0, hh1);
                } else {  // V: transposed hi, dest [b][d=col][l=row&4095]
                    const int b = row >> 12, l = row & 4095;
                    const long long ib = (long long)b * (EMB * SEQ) + l;
                    pp.Oh[ib + (long long)col * SEQ] = hh0;
                    pp.Oh[ib + (long long)(col + 1) * SEQ] = hh1;
                }
            }
        }
    }
}

// ---------------------------------------------------------------------------
// Merged fp32 -> fp16 conversion: segs 0-2 (inputs) hi only; 3-6 (weights) hi+lo
// ---------------------------------------------------------------------------
struct CvtArgs {
    const float4* x[7];
    uint2* h[7];
    uint2* l[7];
};
#define BIG4  (NTOK * EMB / 4)   // 2097152
#define W4    (EMB * EMB / 4)    // 65536
#define CVT_TOT (3 * BIG4 + 4 * W4)

__global__ void cvt_all(CvtArgs args)
{
    int idx = blockIdx.x * 256 + threadIdx.x;
    if (idx >= CVT_TOT) return;
    int seg, off;
    if (idx < 3 * BIG4) { seg = idx / BIG4; off = idx - seg * BIG4; }
    else { int j = idx - 3 * BIG4; seg = 3 + j / W4; off = j & (W4 - 1); }
    float4 v = args.x[seg][off];
    __half h0 = __float2half(v.x), h1 = __float2half(v.y);
    __half h2 = __float2half(v.z), h3 = __float2half(v.w);
    args.h[seg][off] = make_uint2(packh2(h0, h1), packh2(h2, h3));
    if (seg >= 3) {
        __half l0 = __float2half(v.x - __half2float(h0));
        __half l1 = __float2half(v.y - __half2float(h1));
        __half l2 = __float2half(v.z - __half2float(h2));
        __half l3 = __float2half(v.w - __half2float(h3));
        args.l[seg][off] = make_uint2(packh2(l0, l1), packh2(l2, l3));
    }
}

// ---------------------------------------------------------------------------
// softmax over scaled fp16 energy with RAW int32 mask; writes fp16 attn
// ---------------------------------------------------------------------------
__global__ void softmax_kernel(const __half* __restrict__ Eh,
                               const int* __restrict__ mask,
                               __half* __restrict__ Ph)
{
    const long long row = blockIdx.x;
    const uint4* e8 = (const uint4*)(Eh + row * (long long)SEQ);
    const int4* m4 = (const int4*)(mask + row * (long long)SEQ);
    uint4* p8 = (uint4*)(Ph + row * (long long)SEQ);
    const int tid = threadIdx.x;

    float v[16];
    float lmax = -3.0e38f;
#pragma unroll
    for (int i = 0; i < 2; ++i) {
        const int gi = tid + (i << 8);
        const uint4 ev = e8[gi];
        const int4 m0 = m4[2 * gi];
        const int4 m1 = m4[2 * gi + 1];
        const uint32_t ew[4] = {ev.x, ev.y, ev.z, ev.w};
        const int mm[8] = {m0.x, m0.y, m0.z, m0.w, m1.x, m1.y, m1.z, m1.w};
#pragma unroll
        for (int j = 0; j < 4; ++j) {
            const float2 f2 = __half22float2(*(const __half2*)&ew[j]);
            const float a = (mm[2 * j] != 0) ? f2.x : -1.0e20f;
            const float b = (mm[2 * j + 1] != 0) ? f2.y : -1.0e20f;
            v[8 * i + 2 * j] = a;
            v[8 * i + 2 * j + 1] = b;
            lmax = fmaxf(lmax, fmaxf(a, b));
        }
    }

    __shared__ float red[8];
#pragma unroll
    for (int o = 16; o > 0; o >>= 1)
        lmax = fmaxf(lmax, __shfl_xor_sync(0xffffffffu, lmax, o));
    if ((tid & 31) == 0) red[tid >> 5] = lmax;
    __syncthreads();
    float rowmax = red[0];
#pragma unroll
    for (int wv = 1; wv < 8; ++wv) rowmax = fmaxf(rowmax, red[wv]);
    __syncthreads();

    float lsum = 0.f;
#pragma unroll
    for (int i = 0; i < 16; ++i) {
        v[i] = __expf(v[i] - rowmax);
        lsum += v[i];
    }
#pragma unroll
    for (int o = 16; o > 0; o >>= 1)
        lsum += __shfl_xor_sync(0xffffffffu, lsum, o);
    if ((tid & 31) == 0) red[tid >> 5] = lsum;
    __syncthreads();
    float rowsum = 0.f;
#pragma unroll
    for (int wv = 0; wv < 8; ++wv) rowsum += red[wv];
    const float inv = 1.0f / rowsum;

#pragma unroll
    for (int i = 0; i < 2; ++i) {
        const int gi = tid + (i << 8);
        uint4 o;
        o.x = packh2(__float2half(v[8*i+0] * inv), __float2half(v[8*i+1] * inv));
        o.y = packh2(__float2half(v[8*i+2] * inv), __float2half(v[8*i+3] * inv));
        o.z = packh2(__float2half(v[8*i+4] * inv), __float2half(v[8*i+5] * inv));
        o.w = packh2(__float2half(v[8*i+6] * inv), __float2half(v[8*i+7] * inv));
        p8[gi] = o;
    }
}

// ---------------------------------------------------------------------------
// Launch
// ---------------------------------------------------------------------------
extern "C" void kernel_launch(void* const* d_in, const int* in_sizes, int n_in,
                              void* d_out, int out_size)
{
    (void)in_sizes; (void)n_in; (void)out_size;

    const float* values = (const float*)d_in[0];
    const float* keys   = (const float*)d_in[1];
    const float* query  = (const float*)d_in[2];
    const int*   mask   = (const int*)  d_in[3];
    const float* Wv     = (const float*)d_in[4];
    const float* Wk     = (const float*)d_in[5];
    const float* Wq     = (const float*)d_in[6];
    const float* Wo     = (const float*)d_in[7];
    const float* bo     = (const float*)d_in[8];
    float* out = (float*)d_out;

    __half *vh, *kh, *qh;
    __half *Wvh, *Wvl, *Wkh, *Wkl, *Wqh, *Wql, *Woh, *Wol;
    __half *Qph, *Kph, *VTh, *Eh, *Ph, *AOh;
    cudaGetSymbolAddress((void**)&vh, g_vh);
    cudaGetSymbolAddress((void**)&kh, g_kh);
    cudaGetSymbolAddress((void**)&qh, g_qh);
    cudaGetSymbolAddress((void**)&Wvh, g_Wvh); cudaGetSymbolAddress((void**)&Wvl, g_Wvl);
    cudaGetSymbolAddress((void**)&Wkh, g_Wkh); cudaGetSymbolAddress((void**)&Wkl, g_Wkl);
    cudaGetSymbolAddress((void**)&Wqh, g_Wqh); cudaGetSymbolAddress((void**)&Wql, g_Wql);
    cudaGetSymbolAddress((void**)&Woh, g_Woh); cudaGetSymbolAddress((void**)&Wol, g_Wol);
    cudaGetSymbolAddress((void**)&Qph, g_Qph);
    cudaGetSymbolAddress((void**)&Kph, g_Kph);
    cudaGetSymbolAddress((void**)&VTh, g_VTh);
    cudaGetSymbolAddress((void**)&Eh, g_Eh);
    cudaGetSymbolAddress((void**)&Ph, g_Ph);
    cudaGetSymbolAddress((void**)&AOh, g_AOh);

    constexpr int SM1_64 = STAGES1 * 2 * 16384;  // 64 KB (1-term 128x128)
    constexpr int SM1_N64 = 2 * (16384 + 8192);  // 48 KB (1-term 128x64)
    constexpr int SM2_32 = STAGES * 3 * 8192;    // 72 KB (2-term, chunk 32)
    cudaFuncSetAttribute((const void*)mma_gemm1<2>, cudaFuncAttributeMaxDynamicSharedMemorySize, SM1_64);
    cudaFuncSetAttribute((const void*)mma_gemm1_n64, cudaFuncAttributeMaxDynamicSharedMemorySize, SM1_N64);
    cudaFuncSetAttribute((const void*)mma_gemm2_bias, cudaFuncAttributeMaxDynamicSharedMemorySize, SM2_32);
    cudaFuncSetAttribute((const void*)qkv_gemm, cudaFuncAttributeMaxDynamicSharedMemorySize, SM2_32);

    // 1) convert: inputs -> hi fp16; weights -> hi/lo fp16
    CvtArgs ca;
    ca.x[0] = (const float4*)query;  ca.h[0] = (uint2*)qh;  ca.l[0] = nullptr;
    ca.x[1] = (const float4*)keys;   ca.h[1] = (uint2*)kh;  ca.l[1] = nullptr;
    ca.x[2] = (const float4*)values; ca.h[2] = (uint2*)vh;  ca.l[2] = nullptr;
    ca.x[3] = (const float4*)Wq;     ca.h[3] = (uint2*)Wqh; ca.l[3] = (uint2*)Wql;
    ca.x[4] = (const float4*)Wk;     ca.h[4] = (uint2*)Wkh; ca.l[4] = (uint2*)Wkl;
    ca.x[5] = (const float4*)Wv;     ca.h[5] = (uint2*)Wvh; ca.l[5] = (uint2*)Wvl;
    ca.x[6] = (const float4*)Wo;     ca.h[6] = (uint2*)Woh; ca.l[6] = (uint2*)Wol;
    cvt_all<<<(CVT_TOT + 255) / 256, 256>>>(ca);

    const long long sQK = (long long)SEQ * EMB;
    const long long sE  = (long long)SEQ * SEQ;

    // 2) merged projections (2-term): z=0 Q (hi), z=1 K (hi), z=2 V (transposed hi)
    QKVArgs qa;
    qa.p[0] = { qh, Wqh, Wql, Qph };
    qa.p[1] = { kh, Wkh, Wkl, Kph };
    qa.p[2] = { vh, Wvh, Wvl, VTh };
    qkv_gemm<<<dim3(EMB / 128, NTOK / 128, 3), 256, SM2_32>>>(qa);

    // 3) energy: Qph @ Kph^T -> scaled fp16 (128x128 tiles, 4096 CTAs: balanced)
    mma_gemm1<2><<<dim3(SEQ / 128, SEQ / 128, NB), 128, SM1_64>>>(
        Qph, Kph, Eh, EMB, SEQ, sQK, sQK, sE);

    // 4) softmax with raw int32 mask -> attn fp16 (hi only)
    softmax_kernel<<<NB * SEQ, 256>>>(Eh, mask, Ph);

    // 5) attn @ V: Ph @ VTh^T, 128x64 tiles (1024 CTAs, occ 4: wave-balanced)
    mma_gemm1_n64<<<dim3(EMB / 64, SEQ / 128, NB), 128, SM1_N64>>>(
        Ph, VTh, AOh, SEQ, EMB, sE, sQK, sQK);

    // 6) output projection + bias, 2-term (fp32 out)
    mma_gemm2_bias<<<dim3(EMB / 128, NTOK / 128, 1), 256, SM2_32>>>(
        AOh, Woh, Wol, out, bo, EMB, EMB);
}